// round 2
// baseline (speedup 1.0000x reference)
#include <cuda_runtime.h>
#include <cstdint>

// FRIENDATTN: per friend-row n (N=16384):
//   scores[l] = dot(x[n,l,:], self[n/64,:])      (L=50, D=128)
//   w = softmax(scores)                          (mask NOT applied inside softmax)
//   out[n,d] = sum_l w[l] * mask[n,l] * x[n,l,d]
//
// One CTA per row. Stage the 25.6KB row tile in SMEM so HBM is read once.
// Mask dtype is detected at runtime (u8 bool / int32 / int64).

#define D_DIM 128
#define L_DIM 50
#define TPB   128

__device__ int g_mask_mode;   // 0 = u8 bool, 1 = int32, 2 = int64

__global__ void detect_mask_dtype(const int* __restrict__ mw)
{
    // Scan first 2048 int32 words (8 KB; min possible mask buffer = 800 KB).
    __shared__ int s_gt1, s_odd_nz, s_even_nz;
    if (threadIdx.x == 0) { s_gt1 = 0; s_odd_nz = 0; s_even_nz = 0; }
    __syncthreads();

    int gt1 = 0, odd_nz = 0, even_nz = 0;
    for (int i = threadIdx.x; i < 2048; i += blockDim.x) {
        unsigned int v = (unsigned int)mw[i];
        if (v > 1u) gt1 = 1;
        if (v != 0u) { if (i & 1) odd_nz = 1; else even_nz = 1; }
    }
    if (gt1)     atomicOr(&s_gt1, 1);
    if (odd_nz)  atomicOr(&s_odd_nz, 1);
    if (even_nz) atomicOr(&s_even_nz, 1);
    __syncthreads();

    if (threadIdx.x == 0) {
        int mode;
        if (s_gt1)                         mode = 0;  // bytes packed into words
        else if (!s_odd_nz && s_even_nz)   mode = 2;  // int64: high words all zero
        else                               mode = 1;  // int32 0/1
        g_mask_mode = mode;
    }
}

__device__ __forceinline__ bool mask_at(const void* mask, int mode, long long idx)
{
    if (mode == 0) return ((const unsigned char*)mask)[idx] != 0;
    if (mode == 1) return ((const int*)mask)[idx] != 0;
    return ((const int*)mask)[2 * idx] != 0;   // int64, little-endian low word
}

__global__ __launch_bounds__(TPB) void friendattn_kernel(
    const float* __restrict__ x,        // [N, L, D]
    const float* __restrict__ self_x,   // [B, D]
    const void*  __restrict__ mask,     // [N, L] dtype per g_mask_mode
    float* __restrict__ out)            // [N, D]
{
    const int n    = blockIdx.x;
    const int tid  = threadIdx.x;
    const int lane = tid & 31;
    const int warp = tid >> 5;

    __shared__ float sx[L_DIM * D_DIM];      // 25600 B row tile
    __shared__ float sscore[L_DIM];
    __shared__ float sw[L_DIM];              // normalized weight * mask
    __shared__ float sself[D_DIM];

    // ---- load self vector for this row's user (n/64) ----
    sself[tid] = self_x[(size_t)(n >> 6) * D_DIM + tid];

    // ---- stream the row tile into SMEM (fully coalesced float4) ----
    const float4* __restrict__ xrow = (const float4*)(x + (size_t)n * (L_DIM * D_DIM));
    float4* sx4 = (float4*)sx;
    // L*D/4 = 1600 float4 = 12 full passes of 128 threads + 64 remainder
    #pragma unroll
    for (int it = 0; it < 12; ++it) {
        sx4[it * TPB + tid] = xrow[it * TPB + tid];
    }
    if (tid < 64) sx4[12 * TPB + tid] = xrow[12 * TPB + tid];
    __syncthreads();

    // ---- scores: warp w handles l = w, w+4, ... ; lane holds float4 of self ----
    const float4 s4 = ((const float4*)sself)[lane];
    for (int l = warp; l < L_DIM; l += 4) {
        float4 v = ((const float4*)(sx + l * D_DIM))[lane];
        float p = v.x * s4.x + v.y * s4.y + v.z * s4.z + v.w * s4.w;
        #pragma unroll
        for (int o = 16; o > 0; o >>= 1) p += __shfl_xor_sync(0xffffffffu, p, o);
        if (lane == 0) sscore[l] = p;
    }
    __syncthreads();

    // ---- softmax over L=50, mask folded into weights (warp 0 only) ----
    if (warp == 0) {
        const int mode = g_mask_mode;
        const long long mbase = (long long)n * L_DIM;
        float v0 = sscore[lane];                                   // lane < 32 < 50
        float v1 = (lane + 32 < L_DIM) ? sscore[lane + 32] : -3.0e38f;
        float mx = fmaxf(v0, v1);
        #pragma unroll
        for (int o = 16; o > 0; o >>= 1) mx = fmaxf(mx, __shfl_xor_sync(0xffffffffu, mx, o));
        float e0 = __expf(v0 - mx);
        float e1 = (lane + 32 < L_DIM) ? __expf(v1 - mx) : 0.0f;
        float s = e0 + e1;
        #pragma unroll
        for (int o = 16; o > 0; o >>= 1) s += __shfl_xor_sync(0xffffffffu, s, o);
        float inv = 1.0f / s;
        sw[lane] = mask_at(mask, mode, mbase + lane) ? e0 * inv : 0.0f;
        if (lane + 32 < L_DIM)
            sw[lane + 32] = mask_at(mask, mode, mbase + lane + 32) ? e1 * inv : 0.0f;
    }
    __syncthreads();

    // ---- weighted pooling: thread tid owns output dim d=tid ----
    float acc = 0.0f;
    #pragma unroll
    for (int l = 0; l < L_DIM; ++l) {
        acc = fmaf(sw[l], sx[l * D_DIM + tid], acc);
    }
    out[(size_t)n * D_DIM + tid] = acc;
}

extern "C" void kernel_launch(void* const* d_in, const int* in_sizes, int n_in,
                              void* d_out, int out_size)
{
    // metadata order: friend_diff_x, self_x, [friend_num_src], friend_num_src_tensor,
    //                 friend_diff_src_mask (last). Counts are uniform -> ignored.
    const float* x      = (const float*)d_in[0];
    const float* self_x = (const float*)d_in[1];
    const void*  mask   = d_in[n_in - 1];
    float* out = (float*)d_out;

    detect_mask_dtype<<<1, 256>>>((const int*)mask);

    const int N = 256 * 64; // 16384 rows
    friendattn_kernel<<<N, TPB>>>(x, self_x, mask, out);
}

// round 3
// speedup vs baseline: 1.4377x; 1.4377x over previous
#include <cuda_runtime.h>
#include <cstdint>

// FRIENDATTN persistent double-buffered pipeline.
// Per friend-row n (N=16384): scores = x[n]·self[n/64] (L=50,D=128),
// w = softmax(scores); out[n] = sum_l w[l]*mask[n,l]*x[n,l,:].
//
// Stage row tiles (25.6KB) into SMEM via cp.async.cg (L1 bypass), 2-stage
// double buffer, persistent CTAs: compute row i overlaps load of row i+1.

#define D_DIM 128
#define L_DIM 50
#define TPB   128
#define NROWS (256 * 64)
#define GRID  608            // 152 SMs (GB300) * 4 CTAs/SM

// SMEM layout (floats):
//  sx     [2][6400]   @ 0
//  sself  [2][128]    @ 12800
//  sfm    [2][64]     @ 13056
//  sscore [64]        @ 13184
//  sw     [64]        @ 13248
#define SM_FLOATS 13312
#define OFF_SELF  12800
#define OFF_FM    13056
#define OFF_SCORE 13184
#define OFF_W     13248

__device__ int   g_mask_mode;          // 0=u8 bool, 1=int32, 2=int64
__device__ float g_fmask[NROWS * L_DIM];

__global__ void detect_mask_dtype(const int* __restrict__ mw)
{
    __shared__ int s_gt1, s_odd_nz, s_even_nz;
    if (threadIdx.x == 0) { s_gt1 = 0; s_odd_nz = 0; s_even_nz = 0; }
    __syncthreads();
    int gt1 = 0, odd_nz = 0, even_nz = 0;
    for (int i = threadIdx.x; i < 2048; i += blockDim.x) {
        unsigned int v = (unsigned int)mw[i];
        if (v > 1u) gt1 = 1;
        if (v != 0u) { if (i & 1) odd_nz = 1; else even_nz = 1; }
    }
    if (gt1)     atomicOr(&s_gt1, 1);
    if (odd_nz)  atomicOr(&s_odd_nz, 1);
    if (even_nz) atomicOr(&s_even_nz, 1);
    __syncthreads();
    if (threadIdx.x == 0) {
        if (s_gt1)                       g_mask_mode = 0;
        else if (!s_odd_nz && s_even_nz) g_mask_mode = 2;
        else                             g_mask_mode = 1;
    }
}

__global__ void build_fmask(const void* __restrict__ mask)
{
    const int i = blockIdx.x * blockDim.x + threadIdx.x;
    const int total = NROWS * L_DIM;
    if (i >= total) return;
    const int mode = g_mask_mode;
    bool b;
    if (mode == 0)      b = ((const unsigned char*)mask)[i] != 0;
    else if (mode == 1) b = ((const int*)mask)[i] != 0;
    else                b = ((const int*)mask)[2 * (long long)i] != 0;
    g_fmask[i] = b ? 1.0f : 0.0f;
}

__device__ __forceinline__ void cp_async16(float* smem_dst, const float4* gmem_src)
{
    unsigned int s = (unsigned int)__cvta_generic_to_shared(smem_dst);
    asm volatile("cp.async.cg.shared.global [%0], [%1], 16;\n" :: "r"(s), "l"(gmem_src));
}
__device__ __forceinline__ void cp_async8(float* smem_dst, const float* gmem_src)
{
    unsigned int s = (unsigned int)__cvta_generic_to_shared(smem_dst);
    asm volatile("cp.async.ca.shared.global [%0], [%1], 8;\n" :: "r"(s), "l"(gmem_src));
}

__global__ __launch_bounds__(TPB) void friendattn_kernel(
    const float* __restrict__ x,        // [N, L, D]
    const float* __restrict__ self_x,   // [B, D]
    float* __restrict__ out)            // [N, D]
{
    extern __shared__ float smem[];
    const int tid  = threadIdx.x;
    const int lane = tid & 31;
    const int warp = tid >> 5;

    // ---- prefetch helper (lambda-free, inlined) ----
    auto prefetch = [&](int row, int buf) {
        float* sx = smem + buf * (L_DIM * D_DIM);
        const float4* xrow = (const float4*)(x + (size_t)row * (L_DIM * D_DIM));
        #pragma unroll
        for (int it = 0; it < 12; ++it)
            cp_async16(sx + (it * TPB + tid) * 4, xrow + it * TPB + tid);
        if (tid < 64)
            cp_async16(sx + (12 * TPB + tid) * 4, xrow + 12 * TPB + tid);
        if (tid < 32)
            cp_async16(smem + OFF_SELF + buf * D_DIM + tid * 4,
                       (const float4*)(self_x + (size_t)(row >> 6) * D_DIM) + tid);
        if (tid < 25)
            cp_async8(smem + OFF_FM + buf * 64 + tid * 2,
                      g_fmask + (size_t)row * L_DIM + tid * 2);
    };

    int row = blockIdx.x;
    if (row < NROWS) prefetch(row, 0);
    asm volatile("cp.async.commit_group;\n" ::: "memory");

    int buf = 0;
    while (row < NROWS) {
        const int nxt = row + GRID;
        if (nxt < NROWS) prefetch(nxt, buf ^ 1);
        asm volatile("cp.async.commit_group;\n" ::: "memory");
        // wait until only the newest group is still in flight
        asm volatile("cp.async.wait_group 1;\n" ::: "memory");
        __syncthreads();

        const float* sx    = smem + buf * (L_DIM * D_DIM);
        const float* sself = smem + OFF_SELF + buf * D_DIM;
        const float* sfm   = smem + OFF_FM + buf * 64;
        float* sscore = smem + OFF_SCORE;
        float* sw     = smem + OFF_W;

        // ---- scores: warp w handles l = w, w+4, ... ----
        const float4 s4 = ((const float4*)sself)[lane];
        for (int l = warp; l < L_DIM; l += 4) {
            float4 v = ((const float4*)(sx + l * D_DIM))[lane];
            float p = v.x * s4.x + v.y * s4.y + v.z * s4.z + v.w * s4.w;
            #pragma unroll
            for (int o = 16; o > 0; o >>= 1) p += __shfl_xor_sync(0xffffffffu, p, o);
            if (lane == 0) sscore[l] = p;
        }
        __syncthreads();

        // ---- softmax over L=50, mask folded in (warp 0) ----
        if (warp == 0) {
            float v0 = sscore[lane];
            float v1 = (lane + 32 < L_DIM) ? sscore[lane + 32] : -3.0e38f;
            float mx = fmaxf(v0, v1);
            #pragma unroll
            for (int o = 16; o > 0; o >>= 1) mx = fmaxf(mx, __shfl_xor_sync(0xffffffffu, mx, o));
            float e0 = __expf(v0 - mx);
            float e1 = (lane + 32 < L_DIM) ? __expf(v1 - mx) : 0.0f;
            float s = e0 + e1;
            #pragma unroll
            for (int o = 16; o > 0; o >>= 1) s += __shfl_xor_sync(0xffffffffu, s, o);
            float inv = 1.0f / s;
            sw[lane] = e0 * inv * sfm[lane];
            if (lane + 32 < L_DIM)
                sw[lane + 32] = e1 * inv * sfm[lane + 32];
        }
        __syncthreads();

        // ---- weighted pooling: thread tid owns output dim d=tid ----
        float acc = 0.0f;
        #pragma unroll
        for (int l = 0; l < L_DIM; ++l)
            acc = fmaf(sw[l], sx[l * D_DIM + tid], acc);
        out[(size_t)row * D_DIM + tid] = acc;

        __syncthreads();   // protect sscore/sw + sx[buf] reuse next iteration
        buf ^= 1;
        row = nxt;
    }
}

extern "C" void kernel_launch(void* const* d_in, const int* in_sizes, int n_in,
                              void* d_out, int out_size)
{
    const float* x      = (const float*)d_in[0];
    const float* self_x = (const float*)d_in[1];
    const void*  mask   = d_in[n_in - 1];
    float* out = (float*)d_out;

    static bool attr_set = false;
    if (!attr_set) {
        cudaFuncSetAttribute(friendattn_kernel,
                             cudaFuncAttributeMaxDynamicSharedMemorySize,
                             SM_FLOATS * sizeof(float));
        attr_set = true;
    }

    detect_mask_dtype<<<1, 256>>>((const int*)mask);
    build_fmask<<<(NROWS * L_DIM + 255) / 256, 256>>>(mask);
    friendattn_kernel<<<GRID, TPB, SM_FLOATS * sizeof(float)>>>(x, self_x, out);
}